// round 8
// baseline (speedup 1.0000x reference)
#include <cuda_runtime.h>
#include <cstdint>

#define Dn 12
#define Nn 32768
#define Ln 3
#define Kn 4
#define H 128
#define CH 896            // packed output channels per node: 512 f + 128 i + 128 u + 128 o
#define KA 640            // A width: 128 (x) + 512 (h_flat)
#define KE 384            // embedding GEMM K = L*H

// -------- device scratch (no cudaMalloc allowed) --------
__device__ float g_t[Dn * Nn * H];
__device__ float g_act[(size_t)Nn * CH];
__device__ float g_h[2][(Nn + 1) * H];
__device__ float g_c[2][(Nn + 1) * H];
__device__ float g_wp[CH * KA];
__device__ float g_bs[CH];

__device__ __forceinline__ float to_tf32(float x) {
    float r;
    asm("cvt.rna.tf32.f32 %0, %1;" : "=f"(r) : "f"(x));
    return r;
}

__device__ __forceinline__ void mma_tf32(float* d, const uint32_t* a, const uint32_t* b) {
    asm volatile(
        "mma.sync.aligned.m16n8k8.row.col.f32.tf32.tf32.f32 "
        "{%0,%1,%2,%3}, {%4,%5,%6,%7}, {%8,%9}, {%0,%1,%2,%3};"
        : "+f"(d[0]), "+f"(d[1]), "+f"(d[2]), "+f"(d[3])
        : "r"(a[0]), "r"(a[1]), "r"(a[2]), "r"(a[3]), "r"(b[0]), "r"(b[1]));
}

// ---------------- pack per-layer weights (tf32-rounded) ----------------
__global__ void pack_kernel(const float* __restrict__ Uf_w, const float* __restrict__ Uf_b,
                            const float* __restrict__ Uiuo_w, const float* __restrict__ Uiuo_b,
                            const float* __restrict__ W_w, const float* __restrict__ W_b, int l) {
    int c = blockIdx.x;       // 0..895
    int t = threadIdx.x;      // 0..639
    int wrow;
    const float* U;
    float b;
    if (c < 512) {            // f gates
        int j = c & 127;
        wrow = j;
        U = Uf_w + (size_t)(l * 512 + c) * 512;
        b = W_b[l * 512 + j] + Uf_b[l * 512 + c];
    } else {                  // i/u/o
        int q = c - 512;
        wrow = 128 + q;
        U = Uiuo_w + (size_t)(l * 384 + q) * 512;
        b = W_b[l * 512 + 128 + q] + Uiuo_b[l * 384 + q];
    }
    float v = (t < H) ? W_w[(size_t)(l * 512 + wrow) * H + t] : U[t - H];
    g_wp[(size_t)c * KA + t] = to_tf32(v);
    if (t == 0) g_bs[c] = b;
}

// ---------------- zero h/c ping-pong ----------------
__global__ void zero_hc() {
    size_t i = (size_t)blockIdx.x * blockDim.x + threadIdx.x;
    size_t n = (size_t)(Nn + 1) * H;
    if (i < n) {
        g_h[0][i] = 0.f; g_h[1][i] = 0.f;
        g_c[0][i] = 0.f; g_c[1][i] = 0.f;
    }
}

// ---------------- embedding GEMM (FFMA, outputs tf32-rounded) ----------------
__global__ void __launch_bounds__(256) embed_gemm(const int* __restrict__ tokens,
                                                  const float* __restrict__ E,
                                                  const float* __restrict__ lin_w,
                                                  const float* __restrict__ lin_b) {
    __shared__ float As[16][132];
    __shared__ float Bs[16][132];
    int r0 = blockIdx.x * 128;
    int tid = threadIdx.x;
    int tx = tid & 15, ty = tid >> 4;
    float acc[8][8];
#pragma unroll
    for (int i = 0; i < 8; i++)
#pragma unroll
        for (int j = 0; j < 8; j++) acc[i][j] = 0.f;

    int am = tid >> 1;
    int ak = (tid & 1) * 8;
    int row = r0 + am;

    for (int k0 = 0; k0 < KE; k0 += 16) {
        {
            int c = k0 + ak;
            int slot = c >> 7;
            int j = c & 127;
            int tok = tokens[row * Ln + slot];
            const float4* src = (const float4*)(E + (size_t)tok * H + j);
            float4 v0 = src[0], v1 = src[1];
            As[ak + 0][am] = v0.x; As[ak + 1][am] = v0.y; As[ak + 2][am] = v0.z; As[ak + 3][am] = v0.w;
            As[ak + 4][am] = v1.x; As[ak + 5][am] = v1.y; As[ak + 6][am] = v1.z; As[ak + 7][am] = v1.w;
        }
        {
            int cc = tid >> 1;
            int kk = (tid & 1) * 8;
            const float4* src = (const float4*)(lin_w + (size_t)cc * KE + k0 + kk);
            float4 v0 = src[0], v1 = src[1];
            Bs[kk + 0][cc] = v0.x; Bs[kk + 1][cc] = v0.y; Bs[kk + 2][cc] = v0.z; Bs[kk + 3][cc] = v0.w;
            Bs[kk + 4][cc] = v1.x; Bs[kk + 5][cc] = v1.y; Bs[kk + 6][cc] = v1.z; Bs[kk + 7][cc] = v1.w;
        }
        __syncthreads();
#pragma unroll
        for (int k = 0; k < 16; k++) {
            float rm[8], rn[8];
#pragma unroll
            for (int i = 0; i < 8; i++) rm[i] = As[k][ty + i * 16];
#pragma unroll
            for (int j = 0; j < 8; j++) rn[j] = Bs[k][tx + j * 16];
#pragma unroll
            for (int i = 0; i < 8; i++)
#pragma unroll
                for (int j = 0; j < 8; j++) acc[i][j] += rm[i] * rn[j];
        }
        __syncthreads();
    }
#pragma unroll
    for (int i = 0; i < 8; i++) {
        int r = r0 + ty + i * 16;
#pragma unroll
        for (int j = 0; j < 8; j++) {
            int col = tx + j * 16;
            g_t[(size_t)r * H + col] = to_tf32(acc[i][j] + lin_b[col]);
        }
    }
}

// ---------------- per-step GEMM via tf32 mma.sync ----------------
// CTA tile 128x128x16, 4 warps of 64x64, m16n8k8 atoms.
// smem per 8-wide k-group permuted as v0,v4,v1,v5,v2,v6,v3,v7 so each thread's
// (k=q, k=q+4) fragment pair is one contiguous float2 (LDS.64).
__global__ void __launch_bounds__(128, 2) step_gemm(const int* __restrict__ indices, int d, int prev) {
    __shared__ float As[2][128][20];
    __shared__ float Bs[2][128][20];
    int n0 = blockIdx.x * 128;
    int c0 = blockIdx.y * 128;
    int tid = threadIdx.x;
    int warp = tid >> 5;
    int lane = tid & 31;
    int g = lane >> 2;        // groupID (0..7)
    int q = lane & 3;         // thread-in-group
    int wm = (warp & 1) * 64;
    int wn = (warp >> 1) * 64;

    float acc[4][8][4];
#pragma unroll
    for (int i = 0; i < 4; i++)
#pragma unroll
        for (int j = 0; j < 8; j++)
#pragma unroll
            for (int v = 0; v < 4; v++) acc[i][j][v] = 0.f;

    // loaders: thread tid owns A row tid (gathered) and B row tid (weights)
    int row = tid;
    int node = n0 + row;
    const float* hprev = g_h[prev];
    const float* xrow = g_t + ((size_t)d * Nn + node) * H;
    const int4 idxv = *(const int4*)(indices + ((size_t)d * Nn + node) * Kn);
    int safe0 = idxv.x < 0 ? 0 : idxv.x;
    int safe1 = idxv.y < 0 ? 0 : idxv.y;
    int safe2 = idxv.z < 0 ? 0 : idxv.z;
    int safe3 = idxv.w < 0 ? 0 : idxv.w;
    const float* brow = g_wp + (size_t)(c0 + row) * KA;

    float4 a[4], b[4];
    // prologue: k0 = 0 (A chunk entirely in x part)
    {
        const float4* asrc = (const float4*)xrow;
        a[0] = asrc[0]; a[1] = asrc[1]; a[2] = asrc[2]; a[3] = asrc[3];
        const float4* bsrc = (const float4*)brow;
        b[0] = bsrc[0]; b[1] = bsrc[1]; b[2] = bsrc[2]; b[3] = bsrc[3];
    }

#pragma unroll 2
    for (int k0 = 0; k0 < KA; k0 += 16) {
        int s = (k0 >> 4) & 1;
        // store permuted pairs into smem
        {
            float* pA = &As[s][row][0];
            pA[0] = a[0].x;  pA[1] = a[1].x;  pA[2] = a[0].y;  pA[3] = a[1].y;
            pA[4] = a[0].z;  pA[5] = a[1].z;  pA[6] = a[0].w;  pA[7] = a[1].w;
            pA[8] = a[2].x;  pA[9] = a[3].x;  pA[10] = a[2].y; pA[11] = a[3].y;
            pA[12] = a[2].z; pA[13] = a[3].z; pA[14] = a[2].w; pA[15] = a[3].w;
            float* pB = &Bs[s][row][0];
            pB[0] = b[0].x;  pB[1] = b[1].x;  pB[2] = b[0].y;  pB[3] = b[1].y;
            pB[4] = b[0].z;  pB[5] = b[1].z;  pB[6] = b[0].w;  pB[7] = b[1].w;
            pB[8] = b[2].x;  pB[9] = b[3].x;  pB[10] = b[2].y; pB[11] = b[3].y;
            pB[12] = b[2].z; pB[13] = b[3].z; pB[14] = b[2].w; pB[15] = b[3].w;
        }
        __syncthreads();

        // prefetch next 16-k chunk into registers
        if (k0 + 16 < KA) {
            int kk = k0 + 16;
            const float* src;
            if (kk < H) {
                src = xrow + kk;
            } else {
                int kc = (kk - H) >> 7;
                int j0 = (kk - H) & 127;
                int safe = kc == 0 ? safe0 : (kc == 1 ? safe1 : (kc == 2 ? safe2 : safe3));
                src = hprev + (size_t)safe * H + j0;
            }
            const float4* asrc = (const float4*)src;
            a[0] = asrc[0]; a[1] = asrc[1]; a[2] = asrc[2]; a[3] = asrc[3];
            const float4* bsrc = (const float4*)(brow + kk);
            b[0] = bsrc[0]; b[1] = bsrc[1]; b[2] = bsrc[2]; b[3] = bsrc[3];
        }

        // compute: two 8-k chunks
#pragma unroll
        for (int kc = 0; kc < 16; kc += 8) {
            uint32_t afr[4][4];
            uint32_t bfr[8][2];
#pragma unroll
            for (int i = 0; i < 4; i++) {
                int r = wm + i * 16 + g;
                float2 lo = *(const float2*)&As[s][r][kc + 2 * q];
                float2 hi = *(const float2*)&As[s][r + 8][kc + 2 * q];
                afr[i][0] = __float_as_uint(lo.x);
                afr[i][1] = __float_as_uint(hi.x);
                afr[i][2] = __float_as_uint(lo.y);
                afr[i][3] = __float_as_uint(hi.y);
            }
#pragma unroll
            for (int j = 0; j < 8; j++) {
                float2 bv = *(const float2*)&Bs[s][wn + j * 8 + g][kc + 2 * q];
                bfr[j][0] = __float_as_uint(bv.x);
                bfr[j][1] = __float_as_uint(bv.y);
            }
#pragma unroll
            for (int i = 0; i < 4; i++)
#pragma unroll
                for (int j = 0; j < 8; j++)
                    mma_tf32(acc[i][j], afr[i], bfr[j]);
        }
        __syncthreads();
    }

    // epilogue: write pre-activations with bias
#pragma unroll
    for (int i = 0; i < 4; i++) {
        int r = n0 + wm + i * 16 + g;
#pragma unroll
        for (int j = 0; j < 8; j++) {
            int col = c0 + wn + j * 8 + 2 * q;
            float b0 = g_bs[col], b1 = g_bs[col + 1];
            float2 lo = make_float2(acc[i][j][0] + b0, acc[i][j][1] + b1);
            float2 hi = make_float2(acc[i][j][2] + b0, acc[i][j][3] + b1);
            *(float2*)&g_act[(size_t)r * CH + col] = lo;
            *(float2*)&g_act[(size_t)(r + 8) * CH + col] = hi;
        }
    }
}

// ---------------- gate epilogue (h/t writes tf32-rounded for next GEMM) ----------------
__global__ void __launch_bounds__(128) epilogue_kernel(const int* __restrict__ indices, int d, int prev) {
    int n = blockIdx.x;
    int j = threadIdx.x;
    const float* act = g_act + (size_t)n * CH;
    const float* cprev = g_c[prev];
    float* hnext = g_h[prev ^ 1];
    float* cnext = g_c[prev ^ 1];
    const int* idxp = indices + (size_t)(d * Nn + n) * Kn;

    float f = 0.f;
#pragma unroll
    for (int k = 0; k < Kn; k++) {
        int idx = idxp[k];
        int safe = idx < 0 ? 0 : idx;           // row 0 of c_full is zero -> mask implicit
        float cch = cprev[(size_t)safe * H + j];
        float fk = 1.f / (1.f + expf(-act[k * H + j]));
        f += fk * cch;
    }
    float ig = 1.f / (1.f + expf(-act[512 + j]));
    float u = tanhf(act[640 + j]);
    float o = 1.f / (1.f + expf(-act[768 + j]));
    float nc = ig * u + f;
    float nh = o * tanhf(nc);
    hnext[(size_t)(n + 1) * H + j] = to_tf32(nh);
    cnext[(size_t)(n + 1) * H + j] = nc;
    float* tp = g_t + ((size_t)d * Nn + n) * H + j;
    *tp = to_tf32(nh + *tp);
}

// ---------------- final output ----------------
__global__ void final_out(float* __restrict__ out, int lastbuf) {
    size_t i = (size_t)blockIdx.x * blockDim.x + threadIdx.x;
    size_t nh = (size_t)Nn * H;
    if (i < nh) {
        float h = g_t[(size_t)(Dn - 1) * Nn * H + i];
        float c = g_c[lastbuf][H + i];
        out[i] = h;
        out[nh + i] = h;
        out[2 * nh + i] = c;
        out[3 * nh + i] = c;
    }
}

extern "C" void kernel_launch(void* const* d_in, const int* in_sizes, int n_in,
                              void* d_out, int out_size) {
    const int* tokens   = (const int*)d_in[0];
    const int* indices  = (const int*)d_in[1];
    const float* E      = (const float*)d_in[2];
    const float* lin_w  = (const float*)d_in[3];
    const float* lin_b  = (const float*)d_in[4];
    const float* Uf_w   = (const float*)d_in[5];
    const float* Uf_b   = (const float*)d_in[6];
    const float* Uiuo_w = (const float*)d_in[7];
    const float* Uiuo_b = (const float*)d_in[8];
    const float* W_w    = (const float*)d_in[9];
    const float* W_b    = (const float*)d_in[10];
    float* out = (float*)d_out;

    embed_gemm<<<(Dn * Nn) / 128, 256>>>(tokens, E, lin_w, lin_b);

    for (int l = 0; l < 2; l++) {
        pack_kernel<<<CH, KA>>>(Uf_w, Uf_b, Uiuo_w, Uiuo_b, W_w, W_b, l);
        zero_hc<<<(((Nn + 1) * H) + 255) / 256, 256>>>();
        for (int dd = 0; dd < Dn; dd++) {
            step_gemm<<<dim3(Nn / 128, CH / 128), 128>>>(indices, dd, dd & 1);
            epilogue_kernel<<<Nn, H>>>(indices, dd, dd & 1);
        }
    }
    final_out<<<((size_t)Nn * H + 255) / 256, 256>>>(out, 0);
}

// round 9
// speedup vs baseline: 1.6090x; 1.6090x over previous
#include <cuda_runtime.h>
#include <cstdint>

#define Dn 12
#define Nn 32768
#define Ln 3
#define Kn 4
#define H 128
#define CH 896            // packed output channels per node: 512 f + 128 i + 128 u + 128 o
#define KA 640            // A width: 128 (x) + 512 (h_flat)
#define KE 384            // embedding GEMM K = L*H

// -------- device scratch (no cudaMalloc allowed) --------
__device__ float g_t[Dn * Nn * H];
__device__ float g_act[(size_t)Nn * CH];
__device__ float g_h[2][(Nn + 1) * H];
__device__ float g_c[2][(Nn + 1) * H];
__device__ float g_wp[CH * KA];
__device__ float g_bs[CH];

__device__ __forceinline__ float to_tf32(float x) {
    float r;
    asm("cvt.rna.tf32.f32 %0, %1;" : "=f"(r) : "f"(x));
    return r;
}

__device__ __forceinline__ void mma_tf32(float* d, const uint32_t* a, const uint32_t* b) {
    asm volatile(
        "mma.sync.aligned.m16n8k8.row.col.f32.tf32.tf32.f32 "
        "{%0,%1,%2,%3}, {%4,%5,%6,%7}, {%8,%9}, {%0,%1,%2,%3};"
        : "+f"(d[0]), "+f"(d[1]), "+f"(d[2]), "+f"(d[3])
        : "r"(a[0]), "r"(a[1]), "r"(a[2]), "r"(a[3]), "r"(b[0]), "r"(b[1]));
}

// ---------------- pack per-layer weights (tf32-rounded) + zero h/c ----------------
__global__ void pack_kernel(const float* __restrict__ Uf_w, const float* __restrict__ Uf_b,
                            const float* __restrict__ Uiuo_w, const float* __restrict__ Uiuo_b,
                            const float* __restrict__ W_w, const float* __restrict__ W_b, int l) {
    int c = blockIdx.x;       // 0..895 (+extra blocks for zeroing h/c)
    int t = threadIdx.x;      // 0..639
    if (c >= CH) {
        // zero h/c ping-pong: blocks CH.. cover (Nn+1)*H floats
        size_t i = (size_t)(c - CH) * 640 + t;
        size_t n = (size_t)(Nn + 1) * H;
        if (i < n) {
            g_h[0][i] = 0.f; g_h[1][i] = 0.f;
            g_c[0][i] = 0.f; g_c[1][i] = 0.f;
        }
        return;
    }
    int wrow;
    const float* U;
    float b;
    if (c < 512) {            // f gates
        int j = c & 127;
        wrow = j;
        U = Uf_w + (size_t)(l * 512 + c) * 512;
        b = W_b[l * 512 + j] + Uf_b[l * 512 + c];
    } else {                  // i/u/o
        int q = c - 512;
        wrow = 128 + q;
        U = Uiuo_w + (size_t)(l * 384 + q) * 512;
        b = W_b[l * 512 + 128 + q] + Uiuo_b[l * 384 + q];
    }
    float v = (t < H) ? W_w[(size_t)(l * 512 + wrow) * H + t] : U[t - H];
    g_wp[(size_t)c * KA + t] = to_tf32(v);
    if (t == 0) g_bs[c] = b;
}

// ---------------- embedding GEMM via tf32 mma.sync ----------------
// Same core as step_gemm: CTA 128x128x16, 8 warps of 64x32.
// A rows gathered from E via tokens; inputs tf32-rounded in the loader.
__global__ void __launch_bounds__(256) embed_mma(const int* __restrict__ tokens,
                                                 const float* __restrict__ E,
                                                 const float* __restrict__ lin_w,
                                                 const float* __restrict__ lin_b) {
    __shared__ float As[128][20];
    __shared__ float Bs[128][20];
    int r0 = blockIdx.x * 128;
    int tid = threadIdx.x;
    int warp = tid >> 5;
    int lane = tid & 31;
    int g = lane >> 2;
    int q = lane & 3;
    int warp_m = (warp >> 2) * 64;
    int warp_n = (warp & 3) * 32;

    float acc[4][4][4];
#pragma unroll
    for (int i = 0; i < 4; i++)
#pragma unroll
        for (int j = 0; j < 4; j++)
#pragma unroll
            for (int v = 0; v < 4; v++) acc[i][j][v] = 0.f;

    int am = tid >> 1;
    int ak = (tid & 1) * 8;
    int row = r0 + am;
    int tok0 = tokens[row * Ln + 0];
    int tok1 = tokens[row * Ln + 1];
    int tok2 = tokens[row * Ln + 2];
    int cc = tid >> 1;
    int kk = (tid & 1) * 8;
    const float* brow = lin_w + (size_t)cc * KE;

    float4 va0, va1, vb0, vb1;
    {   // prologue k0 = 0 (slot 0)
        const float* src = E + (size_t)tok0 * H + ak;
        va0 = ((const float4*)src)[0];
        va1 = ((const float4*)src)[1];
        const float4* bsrc = (const float4*)(brow + kk);
        vb0 = bsrc[0];
        vb1 = bsrc[1];
    }

    for (int k0 = 0; k0 < KE; k0 += 16) {
        {
            float* pA = &As[am][ak];
            pA[0] = to_tf32(va0.x); pA[1] = to_tf32(va1.x); pA[2] = to_tf32(va0.y); pA[3] = to_tf32(va1.y);
            pA[4] = to_tf32(va0.z); pA[5] = to_tf32(va1.z); pA[6] = to_tf32(va0.w); pA[7] = to_tf32(va1.w);
            float* pB = &Bs[cc][kk];
            pB[0] = to_tf32(vb0.x); pB[1] = to_tf32(vb1.x); pB[2] = to_tf32(vb0.y); pB[3] = to_tf32(vb1.y);
            pB[4] = to_tf32(vb0.z); pB[5] = to_tf32(vb1.z); pB[6] = to_tf32(vb0.w); pB[7] = to_tf32(vb1.w);
        }
        __syncthreads();

        if (k0 + 16 < KE) {
            int c = k0 + 16 + ak;
            int slot = c >> 7;
            int j = c & 127;
            int tok = slot == 0 ? tok0 : (slot == 1 ? tok1 : tok2);
            const float* src = E + (size_t)tok * H + j;
            va0 = ((const float4*)src)[0];
            va1 = ((const float4*)src)[1];
            const float4* bsrc = (const float4*)(brow + k0 + 16 + kk);
            vb0 = bsrc[0];
            vb1 = bsrc[1];
        }

#pragma unroll
        for (int kc = 0; kc < 16; kc += 8) {
            uint32_t afr[4][4];
            uint32_t bfr[4][2];
#pragma unroll
            for (int i = 0; i < 4; i++) {
                int r = warp_m + i * 16 + g;
                float2 lo = *(const float2*)&As[r][kc + 2 * q];
                float2 hi = *(const float2*)&As[r + 8][kc + 2 * q];
                afr[i][0] = __float_as_uint(lo.x);
                afr[i][1] = __float_as_uint(hi.x);
                afr[i][2] = __float_as_uint(lo.y);
                afr[i][3] = __float_as_uint(hi.y);
            }
#pragma unroll
            for (int j = 0; j < 4; j++) {
                float2 bv = *(const float2*)&Bs[warp_n + j * 8 + g][kc + 2 * q];
                bfr[j][0] = __float_as_uint(bv.x);
                bfr[j][1] = __float_as_uint(bv.y);
            }
#pragma unroll
            for (int i = 0; i < 4; i++)
#pragma unroll
                for (int j = 0; j < 4; j++)
                    mma_tf32(acc[i][j], afr[i], bfr[j]);
        }
        __syncthreads();
    }

#pragma unroll
    for (int i = 0; i < 4; i++) {
        int r = r0 + warp_m + i * 16 + g;
#pragma unroll
        for (int j = 0; j < 4; j++) {
            int col = warp_n + j * 8 + 2 * q;
            float b0 = lin_b[col], b1 = lin_b[col + 1];
            float2 lo = make_float2(to_tf32(acc[i][j][0] + b0), to_tf32(acc[i][j][1] + b1));
            float2 hi = make_float2(to_tf32(acc[i][j][2] + b0), to_tf32(acc[i][j][3] + b1));
            *(float2*)&g_t[(size_t)r * H + col] = lo;
            *(float2*)&g_t[(size_t)(r + 8) * H + col] = hi;
        }
    }
}

// ---------------- per-step GEMM via tf32 mma.sync (round-3 proven config) ----------------
// Block tile 128x128x16, 8 warps of 64x32, m16n8k8 atoms.
__global__ void __launch_bounds__(256) step_gemm(const int* __restrict__ indices, int d, int prev) {
    __shared__ float As[128][20];
    __shared__ float Bs[128][20];
    int n0 = blockIdx.x * 128;
    int c0 = blockIdx.y * 128;
    int tid = threadIdx.x;
    int warp = tid >> 5;
    int lane = tid & 31;
    int g = lane >> 2;        // groupID
    int q = lane & 3;         // thread-in-group
    int warp_m = (warp >> 2) * 64;
    int warp_n = (warp & 3) * 32;

    float acc[4][4][4];
#pragma unroll
    for (int i = 0; i < 4; i++)
#pragma unroll
        for (int j = 0; j < 4; j++)
#pragma unroll
            for (int v = 0; v < 4; v++) acc[i][j][v] = 0.f;

    int am = tid >> 1;
    int ak = (tid & 1) * 8;
    int node = n0 + am;
    const float* hprev = g_h[prev];
    const float* xrow = g_t + (size_t)d * Nn * H + (size_t)node * H;
    const int4 idxv = *(const int4*)(indices + (size_t)(d * Nn + node) * Kn);
    int safe0 = idxv.x < 0 ? 0 : idxv.x;
    int safe1 = idxv.y < 0 ? 0 : idxv.y;
    int safe2 = idxv.z < 0 ? 0 : idxv.z;
    int safe3 = idxv.w < 0 ? 0 : idxv.w;
    int cc = tid >> 1;
    int kk = (tid & 1) * 8;
    const float* brow = g_wp + (size_t)(c0 + cc) * KA;

    float4 va0, va1, vb0, vb1;
    {
        const float* src = xrow + ak;
        va0 = ((const float4*)src)[0];
        va1 = ((const float4*)src)[1];
        const float4* bsrc = (const float4*)(brow + kk);
        vb0 = bsrc[0];
        vb1 = bsrc[1];
    }

    for (int k0 = 0; k0 < KA; k0 += 16) {
        {
            float* pA = &As[am][ak];
            pA[0] = va0.x; pA[1] = va1.x; pA[2] = va0.y; pA[3] = va1.y;
            pA[4] = va0.z; pA[5] = va1.z; pA[6] = va0.w; pA[7] = va1.w;
            float* pB = &Bs[cc][kk];
            pB[0] = vb0.x; pB[1] = vb1.x; pB[2] = vb0.y; pB[3] = vb1.y;
            pB[4] = vb0.z; pB[5] = vb1.z; pB[6] = vb0.w; pB[7] = vb1.w;
        }
        __syncthreads();

        if (k0 + 16 < KA) {
            int c = k0 + 16 + ak;
            const float* src;
            if (c < H) {
                src = xrow + c;
            } else {
                int kch = (c - H) >> 7;
                int j = (c - H) & 127;
                int safe = kch == 0 ? safe0 : (kch == 1 ? safe1 : (kch == 2 ? safe2 : safe3));
                src = hprev + (size_t)safe * H + j;
            }
            va0 = ((const float4*)src)[0];
            va1 = ((const float4*)src)[1];
            const float4* bsrc = (const float4*)(brow + k0 + 16 + kk);
            vb0 = bsrc[0];
            vb1 = bsrc[1];
        }

#pragma unroll
        for (int kc = 0; kc < 16; kc += 8) {
            uint32_t afr[4][4];
            uint32_t bfr[4][2];
#pragma unroll
            for (int i = 0; i < 4; i++) {
                int r = warp_m + i * 16 + g;
                float2 lo = *(const float2*)&As[r][kc + 2 * q];
                float2 hi = *(const float2*)&As[r + 8][kc + 2 * q];
                afr[i][0] = __float_as_uint(lo.x);
                afr[i][1] = __float_as_uint(hi.x);
                afr[i][2] = __float_as_uint(lo.y);
                afr[i][3] = __float_as_uint(hi.y);
            }
#pragma unroll
            for (int j = 0; j < 4; j++) {
                float2 bv = *(const float2*)&Bs[warp_n + j * 8 + g][kc + 2 * q];
                bfr[j][0] = __float_as_uint(bv.x);
                bfr[j][1] = __float_as_uint(bv.y);
            }
#pragma unroll
            for (int i = 0; i < 4; i++)
#pragma unroll
                for (int j = 0; j < 4; j++)
                    mma_tf32(acc[i][j], afr[i], bfr[j]);
        }
        __syncthreads();
    }

#pragma unroll
    for (int i = 0; i < 4; i++) {
        int r = n0 + warp_m + i * 16 + g;
#pragma unroll
        for (int j = 0; j < 4; j++) {
            int col = c0 + warp_n + j * 8 + 2 * q;
            float b0 = g_bs[col], b1 = g_bs[col + 1];
            float2 lo = make_float2(acc[i][j][0] + b0, acc[i][j][1] + b1);
            float2 hi = make_float2(acc[i][j][2] + b0, acc[i][j][3] + b1);
            *(float2*)&g_act[(size_t)r * CH + col] = lo;
            *(float2*)&g_act[(size_t)(r + 8) * CH + col] = hi;
        }
    }
}

// ---------------- gate epilogue ----------------
__global__ void __launch_bounds__(128) epilogue_kernel(const int* __restrict__ indices, int d, int prev) {
    int n = blockIdx.x;
    int j = threadIdx.x;
    const float* act = g_act + (size_t)n * CH;
    const float* cprev = g_c[prev];
    float* hnext = g_h[prev ^ 1];
    float* cnext = g_c[prev ^ 1];
    const int* idxp = indices + (size_t)(d * Nn + n) * Kn;

    float f = 0.f;
#pragma unroll
    for (int k = 0; k < Kn; k++) {
        int idx = idxp[k];
        int safe = idx < 0 ? 0 : idx;           // row 0 of c_full is zero -> mask implicit
        float cch = cprev[(size_t)safe * H + j];
        float fk = 1.f / (1.f + __expf(-act[k * H + j]));
        f += fk * cch;
    }
    float ig = 1.f / (1.f + __expf(-act[512 + j]));
    float u = tanhf(act[640 + j]);
    float o = 1.f / (1.f + __expf(-act[768 + j]));
    float nc = ig * u + f;
    float nh = o * tanhf(nc);
    hnext[(size_t)(n + 1) * H + j] = to_tf32(nh);
    cnext[(size_t)(n + 1) * H + j] = nc;
    float* tp = g_t + ((size_t)d * Nn + n) * H + j;
    *tp = to_tf32(nh + *tp);
}

// ---------------- final output ----------------
__global__ void final_out(float* __restrict__ out, int lastbuf) {
    size_t i = (size_t)blockIdx.x * blockDim.x + threadIdx.x;
    size_t nh = (size_t)Nn * H;
    if (i < nh) {
        float h = g_t[(size_t)(Dn - 1) * Nn * H + i];
        float c = g_c[lastbuf][H + i];
        out[i] = h;
        out[nh + i] = h;
        out[2 * nh + i] = c;
        out[3 * nh + i] = c;
    }
}

extern "C" void kernel_launch(void* const* d_in, const int* in_sizes, int n_in,
                              void* d_out, int out_size) {
    const int* tokens   = (const int*)d_in[0];
    const int* indices  = (const int*)d_in[1];
    const float* E      = (const float*)d_in[2];
    const float* lin_w  = (const float*)d_in[3];
    const float* lin_b  = (const float*)d_in[4];
    const float* Uf_w   = (const float*)d_in[5];
    const float* Uf_b   = (const float*)d_in[6];
    const float* Uiuo_w = (const float*)d_in[7];
    const float* Uiuo_b = (const float*)d_in[8];
    const float* W_w    = (const float*)d_in[9];
    const float* W_b    = (const float*)d_in[10];
    float* out = (float*)d_out;

    embed_mma<<<(Dn * Nn) / 128, 256>>>(tokens, E, lin_w, lin_b);

    // pack + zero fused: CH blocks pack weights; extra blocks zero h/c
    int zero_blocks = (int)(((size_t)(Nn + 1) * H + 639) / 640);
    for (int l = 0; l < 2; l++) {
        pack_kernel<<<CH + zero_blocks, KA>>>(Uf_w, Uf_b, Uiuo_w, Uiuo_b, W_w, W_b, l);
        for (int dd = 0; dd < Dn; dd++) {
            step_gemm<<<dim3(Nn / 128, CH / 128), 256>>>(indices, dd, dd & 1);
            epilogue_kernel<<<Nn, H>>>(indices, dd, dd & 1);
        }
    }
    final_out<<<((size_t)Nn * H + 255) / 256, 256>>>(out, 0);
}

// round 10
// speedup vs baseline: 2.7202x; 1.6906x over previous
#include <cuda_runtime.h>
#include <cuda_fp16.h>
#include <cstdint>

#define Dn 12
#define Nn 32768
#define Ln 3
#define Kn 4
#define H 128
#define CH 896            // packed output channels per node: 512 f + 128 i + 128 u + 128 o
#define KA 640            // A width: 128 (x) + 512 (h_flat)
#define KE 384            // embedding GEMM K = L*H

// -------- device scratch (no cudaMalloc allowed) --------
__device__ float  g_t[Dn * Nn * H];              // f32 t (skip/output precision)
__device__ __half g_th[Dn * Nn * H];             // fp16 mirror of t (GEMM A input)
__device__ float  g_act[(size_t)Nn * CH];        // pre-activations for one step
__device__ __half g_h[2][(Nn + 1) * H];          // ping-pong h (fp16, GEMM A input)
__device__ float  g_c[2][(Nn + 1) * H];          // ping-pong c (f32)
__device__ __half g_wp[CH * KA];                 // packed per-layer weights (fp16)
__device__ float  g_bs[CH];                      // packed per-layer bias

__device__ __forceinline__ void mma_f16(float* d, const uint32_t* a, const uint32_t* b) {
    asm volatile(
        "mma.sync.aligned.m16n8k16.row.col.f32.f16.f16.f32 "
        "{%0,%1,%2,%3}, {%4,%5,%6,%7}, {%8,%9}, {%0,%1,%2,%3};"
        : "+f"(d[0]), "+f"(d[1]), "+f"(d[2]), "+f"(d[3])
        : "r"(a[0]), "r"(a[1]), "r"(a[2]), "r"(a[3]), "r"(b[0]), "r"(b[1]));
}

// ---------------- pack per-layer weights (fp16) + zero h/c ----------------
__global__ void pack_kernel(const float* __restrict__ Uf_w, const float* __restrict__ Uf_b,
                            const float* __restrict__ Uiuo_w, const float* __restrict__ Uiuo_b,
                            const float* __restrict__ W_w, const float* __restrict__ W_b, int l) {
    int c = blockIdx.x;       // 0..895 pack; >=CH zero h/c
    int t = threadIdx.x;      // 0..639
    if (c >= CH) {
        size_t i = (size_t)(c - CH) * 640 + t;
        size_t n = (size_t)(Nn + 1) * H;
        if (i < n) {
            g_h[0][i] = __float2half(0.f); g_h[1][i] = __float2half(0.f);
            g_c[0][i] = 0.f; g_c[1][i] = 0.f;
        }
        return;
    }
    int wrow;
    const float* U;
    float b;
    if (c < 512) {            // f gates
        int j = c & 127;
        wrow = j;
        U = Uf_w + (size_t)(l * 512 + c) * 512;
        b = W_b[l * 512 + j] + Uf_b[l * 512 + c];
    } else {                  // i/u/o
        int q = c - 512;
        wrow = 128 + q;
        U = Uiuo_w + (size_t)(l * 384 + q) * 512;
        b = W_b[l * 512 + 128 + q] + Uiuo_b[l * 384 + q];
    }
    float v = (t < H) ? W_w[(size_t)(l * 512 + wrow) * H + t] : U[t - H];
    g_wp[(size_t)c * KA + t] = __float2half(v);
    if (t == 0) g_bs[c] = b;
}

// half-pair helper: pack two floats into one half2 register (as uint)
__device__ __forceinline__ uint32_t f2h2(float a, float b) {
    __half2 h = __floats2half2_rn(a, b);
    return *(uint32_t*)&h;
}

// ---------------- embedding GEMM via fp16 mma.sync ----------------
// CTA 128x128x16, 8 warps of 64x32, m16n8k16 atoms.
// smem layout per 16-k group: slot q holds halves (2q,2q+1,2q+8,2q+9).
__global__ void __launch_bounds__(256) embed_mma(const int* __restrict__ tokens,
                                                 const float* __restrict__ E,
                                                 const float* __restrict__ lin_w,
                                                 const float* __restrict__ lin_b) {
    __shared__ __half As[128][20];
    __shared__ __half Bs[128][20];
    int r0 = blockIdx.x * 128;
    int tid = threadIdx.x;
    int warp = tid >> 5;
    int lane = tid & 31;
    int g = lane >> 2;
    int q = lane & 3;
    int warp_m = (warp >> 2) * 64;
    int warp_n = (warp & 3) * 32;

    float acc[4][4][4];
#pragma unroll
    for (int i = 0; i < 4; i++)
#pragma unroll
        for (int j = 0; j < 4; j++)
#pragma unroll
            for (int v = 0; v < 4; v++) acc[i][j][v] = 0.f;

    int am = tid >> 1;
    int hh = tid & 1;               // which 8-half subchunk (0..7 or 8..15)
    int row = r0 + am;
    int tok0 = tokens[row * Ln + 0];
    int tok1 = tokens[row * Ln + 1];
    int tok2 = tokens[row * Ln + 2];
    const float* brow = lin_w + (size_t)am * KE;

    float4 va0, va1, vb0, vb1;
    {   // prologue k0 = 0 (slot 0)
        const float* src = E + (size_t)tok0 * H + hh * 8;
        va0 = ((const float4*)src)[0];
        va1 = ((const float4*)src)[1];
        const float4* bsrc = (const float4*)(brow + hh * 8);
        vb0 = bsrc[0];
        vb1 = bsrc[1];
    }

    for (int k0 = 0; k0 < KE; k0 += 16) {
        {   // permuted store: pair p of this subchunk -> uint index 2p + hh
            uint32_t* pA = (uint32_t*)&As[am][0];
            pA[0 + hh] = f2h2(va0.x, va0.y);
            pA[2 + hh] = f2h2(va0.z, va0.w);
            pA[4 + hh] = f2h2(va1.x, va1.y);
            pA[6 + hh] = f2h2(va1.z, va1.w);
            uint32_t* pB = (uint32_t*)&Bs[am][0];
            pB[0 + hh] = f2h2(vb0.x, vb0.y);
            pB[2 + hh] = f2h2(vb0.z, vb0.w);
            pB[4 + hh] = f2h2(vb1.x, vb1.y);
            pB[6 + hh] = f2h2(vb1.z, vb1.w);
        }
        __syncthreads();

        if (k0 + 16 < KE) {
            int c = k0 + 16 + hh * 8;
            int slot = c >> 7;
            int j = c & 127;
            int tok = slot == 0 ? tok0 : (slot == 1 ? tok1 : tok2);
            const float* src = E + (size_t)tok * H + j;
            va0 = ((const float4*)src)[0];
            va1 = ((const float4*)src)[1];
            const float4* bsrc = (const float4*)(brow + k0 + 16 + hh * 8);
            vb0 = bsrc[0];
            vb1 = bsrc[1];
        }

        {
            uint32_t afr[4][4];
            uint32_t bfr[4][2];
#pragma unroll
            for (int i = 0; i < 4; i++) {
                int r = warp_m + i * 16 + g;
                uint2 lo = *(const uint2*)&As[r][4 * q];
                uint2 hi = *(const uint2*)&As[r + 8][4 * q];
                afr[i][0] = lo.x; afr[i][1] = hi.x; afr[i][2] = lo.y; afr[i][3] = hi.y;
            }
#pragma unroll
            for (int j = 0; j < 4; j++) {
                uint2 bv = *(const uint2*)&Bs[warp_n + j * 8 + g][4 * q];
                bfr[j][0] = bv.x; bfr[j][1] = bv.y;
            }
#pragma unroll
            for (int i = 0; i < 4; i++)
#pragma unroll
                for (int j = 0; j < 4; j++)
                    mma_f16(acc[i][j], afr[i], bfr[j]);
        }
        __syncthreads();
    }

#pragma unroll
    for (int i = 0; i < 4; i++) {
        int r = r0 + warp_m + i * 16 + g;
#pragma unroll
        for (int j = 0; j < 4; j++) {
            int col = warp_n + j * 8 + 2 * q;
            float b0 = lin_b[col], b1 = lin_b[col + 1];
            float lo0 = acc[i][j][0] + b0, lo1 = acc[i][j][1] + b1;
            float hi0 = acc[i][j][2] + b0, hi1 = acc[i][j][3] + b1;
            *(float2*)&g_t[(size_t)r * H + col] = make_float2(lo0, lo1);
            *(float2*)&g_t[(size_t)(r + 8) * H + col] = make_float2(hi0, hi1);
            *(uint32_t*)&g_th[(size_t)r * H + col] = f2h2(lo0, lo1);
            *(uint32_t*)&g_th[(size_t)(r + 8) * H + col] = f2h2(hi0, hi1);
        }
    }
}

// ---------------- per-step GEMM via fp16 mma.sync ----------------
// CTA 128x128x16, 8 warps of 64x32, m16n8k16 atoms.
__global__ void __launch_bounds__(256) step_gemm(const int* __restrict__ indices, int d, int prev) {
    __shared__ __half As[128][20];
    __shared__ __half Bs[128][20];
    int n0 = blockIdx.x * 128;
    int c0 = blockIdx.y * 128;
    int tid = threadIdx.x;
    int warp = tid >> 5;
    int lane = tid & 31;
    int g = lane >> 2;
    int q = lane & 3;
    int warp_m = (warp >> 2) * 64;
    int warp_n = (warp & 3) * 32;

    float acc[4][4][4];
#pragma unroll
    for (int i = 0; i < 4; i++)
#pragma unroll
        for (int j = 0; j < 4; j++)
#pragma unroll
            for (int v = 0; v < 4; v++) acc[i][j][v] = 0.f;

    int am = tid >> 1;
    int hh = tid & 1;
    int node = n0 + am;
    const __half* hprev = g_h[prev];
    const __half* xrow = g_th + ((size_t)d * Nn + node) * H;
    const int4 idxv = *(const int4*)(indices + ((size_t)d * Nn + node) * Kn);
    int safe0 = idxv.x < 0 ? 0 : idxv.x;
    int safe1 = idxv.y < 0 ? 0 : idxv.y;
    int safe2 = idxv.z < 0 ? 0 : idxv.z;
    int safe3 = idxv.w < 0 ? 0 : idxv.w;
    const __half* brow = g_wp + (size_t)(c0 + am) * KA;

    uint4 va, vb;
    {   // prologue: k0 = 0 (x part)
        va = *(const uint4*)(xrow + hh * 8);
        vb = *(const uint4*)(brow + hh * 8);
    }

    for (int k0 = 0; k0 < KA; k0 += 16) {
        {   // permuted store: 8 halves = 4 half2 words at uint index 2p + hh
            uint32_t* pA = (uint32_t*)&As[am][0];
            pA[0 + hh] = va.x; pA[2 + hh] = va.y; pA[4 + hh] = va.z; pA[6 + hh] = va.w;
            uint32_t* pB = (uint32_t*)&Bs[am][0];
            pB[0 + hh] = vb.x; pB[2 + hh] = vb.y; pB[4 + hh] = vb.z; pB[6 + hh] = vb.w;
        }
        __syncthreads();

        if (k0 + 16 < KA) {
            int c = k0 + 16 + hh * 8;
            const __half* src;
            if (c < H) {
                src = xrow + c;
            } else {
                int kch = (c - H) >> 7;
                int j = (c - H) & 127;
                int safe = kch == 0 ? safe0 : (kch == 1 ? safe1 : (kch == 2 ? safe2 : safe3));
                src = hprev + (size_t)safe * H + j;
            }
            va = *(const uint4*)src;
            vb = *(const uint4*)(brow + k0 + 16 + hh * 8);
        }

        {
            uint32_t afr[4][4];
            uint32_t bfr[4][2];
#pragma unroll
            for (int i = 0; i < 4; i++) {
                int r = warp_m + i * 16 + g;
                uint2 lo = *(const uint2*)&As[r][4 * q];
                uint2 hi = *(const uint2*)&As[r + 8][4 * q];
                afr[i][0] = lo.x; afr[i][1] = hi.x; afr[i][2] = lo.y; afr[i][3] = hi.y;
            }
#pragma unroll
            for (int j = 0; j < 4; j++) {
                uint2 bv = *(const uint2*)&Bs[warp_n + j * 8 + g][4 * q];
                bfr[j][0] = bv.x; bfr[j][1] = bv.y;
            }
#pragma unroll
            for (int i = 0; i < 4; i++)
#pragma unroll
                for (int j = 0; j < 4; j++)
                    mma_f16(acc[i][j], afr[i], bfr[j]);
        }
        __syncthreads();
    }

#pragma unroll
    for (int i = 0; i < 4; i++) {
        int r = n0 + warp_m + i * 16 + g;
#pragma unroll
        for (int j = 0; j < 4; j++) {
            int col = c0 + warp_n + j * 8 + 2 * q;
            float b0 = g_bs[col], b1 = g_bs[col + 1];
            float2 lo = make_float2(acc[i][j][0] + b0, acc[i][j][1] + b1);
            float2 hi = make_float2(acc[i][j][2] + b0, acc[i][j][3] + b1);
            *(float2*)&g_act[(size_t)r * CH + col] = lo;
            *(float2*)&g_act[(size_t)(r + 8) * CH + col] = hi;
        }
    }
}

// ---------------- gate epilogue ----------------
__global__ void __launch_bounds__(128) epilogue_kernel(const int* __restrict__ indices, int d, int prev) {
    int n = blockIdx.x;
    int j = threadIdx.x;
    const float* act = g_act + (size_t)n * CH;
    const float* cprev = g_c[prev];
    __half* hnext = g_h[prev ^ 1];
    float* cnext = g_c[prev ^ 1];
    const int* idxp = indices + (size_t)(d * Nn + n) * Kn;

    float f = 0.f;
#pragma unroll
    for (int k = 0; k < Kn; k++) {
        int idx = idxp[k];
        int safe = idx < 0 ? 0 : idx;           // row 0 of c is zero -> mask implicit
        float cch = cprev[(size_t)safe * H + j];
        float fk = 1.f / (1.f + __expf(-act[k * H + j]));
        f += fk * cch;
    }
    float ig = 1.f / (1.f + __expf(-act[512 + j]));
    float u = tanhf(act[640 + j]);
    float o = 1.f / (1.f + __expf(-act[768 + j]));
    float nc = ig * u + f;
    float nh = o * tanhf(nc);
    hnext[(size_t)(n + 1) * H + j] = __float2half(nh);
    cnext[(size_t)(n + 1) * H + j] = nc;
    size_t tpos = ((size_t)d * Nn + n) * H + j;
    float tn = nh + g_t[tpos];                   // skip connection
    g_t[tpos] = tn;
    g_th[tpos] = __float2half(tn);
}

// ---------------- final output ----------------
__global__ void final_out(float* __restrict__ out, int lastbuf) {
    size_t i = (size_t)blockIdx.x * blockDim.x + threadIdx.x;
    size_t nh = (size_t)Nn * H;
    if (i < nh) {
        float h = g_t[(size_t)(Dn - 1) * Nn * H + i];
        float c = g_c[lastbuf][H + i];
        out[i] = h;
        out[nh + i] = h;
        out[2 * nh + i] = c;
        out[3 * nh + i] = c;
    }
}

extern "C" void kernel_launch(void* const* d_in, const int* in_sizes, int n_in,
                              void* d_out, int out_size) {
    const int* tokens   = (const int*)d_in[0];
    const int* indices  = (const int*)d_in[1];
    const float* E      = (const float*)d_in[2];
    const float* lin_w  = (const float*)d_in[3];
    const float* lin_b  = (const float*)d_in[4];
    const float* Uf_w   = (const float*)d_in[5];
    const float* Uf_b   = (const float*)d_in[6];
    const float* Uiuo_w = (const float*)d_in[7];
    const float* Uiuo_b = (const float*)d_in[8];
    const float* W_w    = (const float*)d_in[9];
    const float* W_b    = (const float*)d_in[10];
    float* out = (float*)d_out;

    embed_mma<<<(Dn * Nn) / 128, 256>>>(tokens, E, lin_w, lin_b);

    int zero_blocks = (int)(((size_t)(Nn + 1) * H + 639) / 640);
    for (int l = 0; l < 2; l++) {
        pack_kernel<<<CH + zero_blocks, KA>>>(Uf_w, Uf_b, Uiuo_w, Uiuo_b, W_w, W_b, l);
        for (int dd = 0; dd < Dn; dd++) {
            step_gemm<<<dim3(Nn / 128, CH / 128), 256>>>(indices, dd, dd & 1);
            epilogue_kernel<<<Nn, H>>>(indices, dd, dd & 1);
        }
    }
    final_out<<<((size_t)Nn * H + 255) / 256, 256>>>(out, 0);
}